// round 2
// baseline (speedup 1.0000x reference)
#include <cuda_runtime.h>
#include <cstdint>
#include <cstddef>

#define T_SEQ   256
#define BATCH   64
#define DIN     200
#define HIDN    300
#define NLAYERS 8
#define G5      1500
#define G6      1800
#define TBROWS  (T_SEQ*BATCH)           // 16384
#define OUT_SZ  (BATCH*T_SEQ*HIDN)      // 4,915,200
#define LAYER_SZ (T_SEQ*BATCH*HIDN)     // 4,915,200
#define HID_SZ  (NLAYERS*LAYER_SZ)      // 39,321,600
#define NCTA_SCAN 100

// Scratch (device globals: no runtime allocation allowed)
__device__ float g_pi[(size_t)TBROWS * G6];       // [T*B, 1800] input projections
__device__ float g_hbuf[2 * HIDN * BATCH];        // double-buffered h, [k][b] transposed
__device__ int   g_bar[NLAYERS * T_SEQ];          // grid-barrier counters per (layer, t)

// ---------------------------------------------------------------------------
// GEMM: g_pi[r, :] = A[r, :] @ W   (M=16384, N=1800, K=200 or 300)
// Layer 0: A row r -> inputs[b, t, :] with b=r%64, t=r/64 (transpose folded in)
// ---------------------------------------------------------------------------
__global__ void __launch_bounds__(256) sgemm_pi(
    const float* __restrict__ Abase, const float* __restrict__ W,
    int K, int a_l0)
{
    __shared__ float As[8][132];
    __shared__ float Bs[8][64];
    const int tid = threadIdx.x;
    const int bn = blockIdx.x * 64;
    const int bm = blockIdx.y * 128;
    const int tx = tid & 15, ty = tid >> 4;

    float acc[8][4];
    #pragma unroll
    for (int i = 0; i < 8; i++)
        #pragma unroll
        for (int j = 0; j < 4; j++) acc[i][j] = 0.f;

    // A-load mapping: each thread loads one float4 (row = tid/2, 4 k's)
    const int arow = tid >> 1;
    const int ac4  = (tid & 1) * 4;
    const int r    = bm + arow;
    const float* Arow;
    if (a_l0) {
        int b = r & 63, t = r >> 6;
        Arow = Abase + ((size_t)b * T_SEQ + t) * DIN;
    } else {
        Arow = Abase + (size_t)r * HIDN;
    }

    for (int k0 = 0; k0 < K; k0 += 8) {
        // ---- global loads into registers ----
        float4 av;
        {
            int kc = k0 + ac4;
            if (kc + 3 < K) {
                av = *(const float4*)(Arow + kc);
            } else {
                av.x = (kc     < K) ? Arow[kc]     : 0.f;
                av.y = (kc + 1 < K) ? Arow[kc + 1] : 0.f;
                av.z = (kc + 2 < K) ? Arow[kc + 2] : 0.f;
                av.w = (kc + 3 < K) ? Arow[kc + 3] : 0.f;
            }
        }
        float4 bv = make_float4(0.f, 0.f, 0.f, 0.f);
        if (tid < 128) {
            int bk = k0 + (tid >> 4);
            int bc = bn + (tid & 15) * 4;
            if (bk < K) {
                const float* Wr = W + (size_t)bk * G6;
                if (bc + 3 < G6) {
                    bv = *(const float4*)(Wr + bc);
                } else {
                    if (bc     < G6) bv.x = Wr[bc];
                    if (bc + 1 < G6) bv.y = Wr[bc + 1];
                    if (bc + 2 < G6) bv.z = Wr[bc + 2];
                    if (bc + 3 < G6) bv.w = Wr[bc + 3];
                }
            }
        }
        __syncthreads();
        // ---- stage to smem ----
        As[ac4 + 0][arow] = av.x;
        As[ac4 + 1][arow] = av.y;
        As[ac4 + 2][arow] = av.z;
        As[ac4 + 3][arow] = av.w;
        if (tid < 128)
            *(float4*)&Bs[tid >> 4][(tid & 15) * 4] = bv;
        __syncthreads();
        // ---- compute 128x64x8 ----
        #pragma unroll
        for (int k = 0; k < 8; k++) {
            float4 A0 = *(const float4*)&As[k][ty * 8];
            float4 A1 = *(const float4*)&As[k][ty * 8 + 4];
            float4 B0 = *(const float4*)&Bs[k][tx * 4];
            float a[8] = {A0.x, A0.y, A0.z, A0.w, A1.x, A1.y, A1.z, A1.w};
            float bb[4] = {B0.x, B0.y, B0.z, B0.w};
            #pragma unroll
            for (int i = 0; i < 8; i++)
                #pragma unroll
                for (int j = 0; j < 4; j++)
                    acc[i][j] += a[i] * bb[j];
        }
    }

    // ---- store ----
    #pragma unroll
    for (int i = 0; i < 8; i++) {
        int row = bm + ty * 8 + i;
        float* orow = g_pi + (size_t)row * G6;
        int c0 = bn + tx * 4;
        if (c0 + 3 < G6) {
            float4 v = make_float4(acc[i][0], acc[i][1], acc[i][2], acc[i][3]);
            *(float4*)(orow + c0) = v;
        } else {
            #pragma unroll
            for (int j = 0; j < 4; j++)
                if (c0 + j < G6) orow[c0 + j] = acc[i][j];
        }
    }
}

// ---------------------------------------------------------------------------
// Persistent recurrent scan: 100 CTAs, each owns 3 h-columns (x5 gates).
// Threads: b = tid&63, ks = tid>>6 (4-way k split of the H=300 reduction).
// One grid barrier per timestep; h double-buffered in g_hbuf (transposed [k][b]).
// ---------------------------------------------------------------------------
__global__ void __launch_bounds__(256) lstm_scan(
    const float* __restrict__ Whh,   // [300][1500] this layer
    const float* __restrict__ bias,  // [1500]
    const int*   __restrict__ lengths,
    float*       __restrict__ ys,    // hidden slice [T][B][H]
    int reverse, int* __restrict__ bar)
{
    __shared__ float sW[300 * 16];         // [k][g*3+jl], padded to 16
    __shared__ float sred[4][64][17];      // partial z, padded stride 17

    const int tid = threadIdx.x;
    const int j0  = blockIdx.x * 3;
    const int b   = tid & 63;
    const int ks  = tid >> 6;

    // Stage weight slice: sW[k*16 + g*3+jl] = Whh[k][g*300 + j0+jl]
    for (int idx = tid; idx < 300 * 16; idx += 256) {
        int k = idx >> 4, c = idx & 15;
        float v = 0.f;
        if (c < 15) {
            int g = c / 3, jl = c % 3;
            v = Whh[(size_t)k * G5 + g * HIDN + j0 + jl];
        }
        sW[idx] = v;
    }

    // Pointwise-owner persistent state (threads 0..191: one (b, j) each)
    float c_st = 0.f, h_st = 0.f;
    float bi[5] = {0.f, 0.f, 0.f, 0.f, 0.f};
    int len = 0, jl = 0, jj = 0;
    if (tid < 192) {
        jl = tid >> 6;           // 0..2
        jj = j0 + jl;
        len = lengths[b];
        #pragma unroll
        for (int g = 0; g < 5; g++) bi[g] = bias[g * HIDN + jj];
    }
    __syncthreads();

    int p = 0;
    for (int t = 0; t < T_SEQ; t++) {
        // ---- partial z = h @ W over this thread's k-range ----
        float acc[16];
        #pragma unroll
        for (int c = 0; c < 16; c++) acc[c] = 0.f;
        if (t > 0) {
            const float* hb = g_hbuf + p * (HIDN * BATCH);
            const int kbeg = ks * 75;
            #pragma unroll 5
            for (int k = kbeg; k < kbeg + 75; k++) {
                float hv = __ldcg(&hb[k * 64 + b]);   // L2 (coherent across SMs)
                const float4* w4 = (const float4*)(sW + (k << 4));
                float4 w0 = w4[0], w1 = w4[1], w2 = w4[2], w3 = w4[3];
                acc[0]  += hv * w0.x;  acc[1]  += hv * w0.y;
                acc[2]  += hv * w0.z;  acc[3]  += hv * w0.w;
                acc[4]  += hv * w1.x;  acc[5]  += hv * w1.y;
                acc[6]  += hv * w1.z;  acc[7]  += hv * w1.w;
                acc[8]  += hv * w2.x;  acc[9]  += hv * w2.y;
                acc[10] += hv * w2.z;  acc[11] += hv * w2.w;
                acc[12] += hv * w3.x;  acc[13] += hv * w3.y;
                acc[14] += hv * w3.z;
            }
        }
        #pragma unroll
        for (int c = 0; c < 15; c++) sred[ks][b][c] = acc[c];
        __syncthreads();

        // ---- pointwise gates ----
        if (tid < 192) {
            float z[5];
            #pragma unroll
            for (int g = 0; g < 5; g++) {
                int c = g * 3 + jl;
                z[g] = bi[g] + sred[0][b][c] + sred[1][b][c]
                             + sred[2][b][c] + sred[3][b][c];
            }
            int tr  = reverse ? (len - 1 - t) : t;
            int trc = tr < 0 ? 0 : tr;
            const float* pirow = g_pi + ((size_t)trc * BATCH + b) * G6;
            z[0] += pirow[jj];
            z[1] += pirow[HIDN + jj];
            z[2] += pirow[2 * HIDN + jj];
            z[3] += pirow[3 * HIDN + jj];
            z[4] += pirow[4 * HIDN + jj];
            float pih = pirow[5 * HIDN + jj];

            float ig = 1.f / (1.f + __expf(-z[0]));
            float fg = 1.f / (1.f + __expf(-z[1]));
            float gg = tanhf(z[2]);
            float og = 1.f / (1.f + __expf(-z[3]));
            float rg = 1.f / (1.f + __expf(-z[4]));
            float cn = ig * gg + fg * c_st;
            float lo = og * tanhf(cn);
            float hn = rg * lo + (1.f - rg) * pih;

            if (t < len) {
                c_st = cn;
                h_st = hn;
                int tout = reverse ? tr : t;   // tr >= 0 here since t < len
                ys[((size_t)tout * BATCH + b) * HIDN + jj] = hn;
            }
            __stcg(&g_hbuf[(1 - p) * (HIDN * BATCH) + jj * 64 + b], h_st);
        }

        // ---- grid barrier (release/acquire, per-(layer,t) counter) ----
        __syncthreads();
        if (tid == 0) {
            int* ctr = bar + t;
            asm volatile("red.release.gpu.global.add.s32 [%0], 1;"
                         :: "l"(ctr) : "memory");
            int v;
            do {
                asm volatile("ld.acquire.gpu.global.s32 %0, [%1];"
                             : "=r"(v) : "l"(ctr) : "memory");
                if (v < NCTA_SCAN) __nanosleep(32);
            } while (v < NCTA_SCAN);
        }
        __syncthreads();
        p ^= 1;
    }
}

// ---------------------------------------------------------------------------
// output[b, t, h] = hidden[7][t, b, h]
// ---------------------------------------------------------------------------
__global__ void __launch_bounds__(256) transpose_out(
    const float* __restrict__ hid7, float* __restrict__ out)
{
    int i = blockIdx.x * 256 + threadIdx.x;
    if (i >= LAYER_SZ) return;
    int h = i % HIDN;
    int r = i / HIDN;      // r = t*B + b
    int b = r % BATCH;
    int t = r / BATCH;
    out[((size_t)b * T_SEQ + t) * HIDN + h] = hid7[i];
}

// ---------------------------------------------------------------------------
extern "C" void kernel_launch(void* const* d_in, const int* in_sizes, int n_in,
                              void* d_out, int out_size)
{
    const float* inputs  = (const float*)d_in[0];
    const int*   lengths = (const int*)  d_in[1];
    const float* Wih0    = (const float*)d_in[2];
    const float* Wihr    = (const float*)d_in[3];
    const float* Whh     = (const float*)d_in[4];
    const float* bhh     = (const float*)d_in[5];
    float* out    = (float*)d_out;
    float* hidden = out + OUT_SZ;

    int* barp = nullptr;
    cudaGetSymbolAddress((void**)&barp, g_bar);

    // Zero padded region of hidden (valid entries overwritten below) and
    // barrier counters (must reset on every graph replay).
    cudaMemsetAsync(hidden, 0, (size_t)HID_SZ * sizeof(float), 0);
    cudaMemsetAsync(barp, 0, NLAYERS * T_SEQ * sizeof(int), 0);

    for (int l = 0; l < NLAYERS; l++) {
        const float* A;
        int K, a_l0;
        if (l == 0) { A = inputs; K = DIN; a_l0 = 1; }
        else {
            A = hidden + (size_t)(l - 1) * LAYER_SZ;
            K = HIDN; a_l0 = 0;
        }
        const float* Wih = (l == 0) ? Wih0 : (Wihr + (size_t)(l - 1) * HIDN * G6);

        dim3 ggrid((G6 + 63) / 64, TBROWS / 128);
        sgemm_pi<<<ggrid, 256>>>(A, Wih, K, a_l0);

        lstm_scan<<<NCTA_SCAN, 256>>>(
            Whh + (size_t)l * HIDN * G5,
            bhh + (size_t)l * G5,
            lengths,
            hidden + (size_t)l * LAYER_SZ,
            l & 1,
            barp + l * T_SEQ);
    }

    transpose_out<<<(LAYER_SZ + 255) / 256, 256>>>(
        hidden + (size_t)(NLAYERS - 1) * LAYER_SZ, out);
}

// round 5
// speedup vs baseline: 1.1757x; 1.1757x over previous
#include <cuda_runtime.h>
#include <cuda_bf16.h>
#include <cstdint>
#include <cstddef>

#define T_SEQ   256
#define BATCH   64
#define DIN     200
#define HIDN    300
#define NLAYERS 8
#define G5      1500
#define G6      1800
#define NPAD    1920
#define TBROWS  (T_SEQ*BATCH)           // 16384
#define OUT_SZ  (BATCH*T_SEQ*HIDN)
#define LAYER_SZ (T_SEQ*BATCH*HIDN)
#define NCTA_SCAN 100
#define KPAD_MAX 320

// ---- scratch (device globals; no runtime allocation allowed) ----
__device__ float         g_pi[(size_t)NPAD * TBROWS];   // TRANSPOSED: [col][t*64+b]
__device__ __nv_bfloat16 g_Ah[(size_t)TBROWS * KPAD_MAX];
__device__ __nv_bfloat16 g_Al[(size_t)TBROWS * KPAD_MAX];
__device__ __nv_bfloat16 g_Wh[(size_t)NPAD * KPAD_MAX];
__device__ __nv_bfloat16 g_Wl[(size_t)NPAD * KPAD_MAX];
__device__ float         g_hbuf[2 * HIDN * BATCH];
__device__ int           g_bar[NLAYERS * T_SEQ];

// ============================ PTX helpers ============================
__device__ __forceinline__ uint32_t smem_u32(const void* p) {
    uint32_t a;
    asm("{ .reg .u64 t; cvta.to.shared.u64 t, %1; cvt.u32.u64 %0, t; }"
        : "=r"(a) : "l"(p));
    return a;
}
__device__ __forceinline__ void cp16(uint32_t dst, const void* src) {
    asm volatile("cp.async.cg.shared.global [%0], [%1], 16;"
                 :: "r"(dst), "l"(src) : "memory");
}
__device__ __forceinline__ void cp_commit() {
    asm volatile("cp.async.commit_group;" ::: "memory");
}
template <int N>
__device__ __forceinline__ void cp_wait() {
    asm volatile("cp.async.wait_group %0;" :: "n"(N) : "memory");
}
__device__ __forceinline__ void ldsm4(uint32_t* r, uint32_t addr) {
    asm volatile("ldmatrix.sync.aligned.m8n8.x4.shared.b16 {%0,%1,%2,%3}, [%4];"
                 : "=r"(r[0]), "=r"(r[1]), "=r"(r[2]), "=r"(r[3]) : "r"(addr));
}
__device__ __forceinline__ void mma_bf16(float* c, const uint32_t* a, const uint32_t* b) {
    asm volatile(
        "mma.sync.aligned.m16n8k16.row.col.f32.bf16.bf16.f32 "
        "{%0,%1,%2,%3}, {%4,%5,%6,%7}, {%8,%9}, {%0,%1,%2,%3};"
        : "+f"(c[0]), "+f"(c[1]), "+f"(c[2]), "+f"(c[3])
        : "r"(a[0]), "r"(a[1]), "r"(a[2]), "r"(a[3]), "r"(b[0]), "r"(b[1]));
}

// ========================= conversion kernels =========================
__global__ void __launch_bounds__(256) conv_A(
    const float* __restrict__ src, __nv_bfloat16* __restrict__ hi,
    __nv_bfloat16* __restrict__ lo, int K, int Kpad, int l0)
{
    int warp = (blockIdx.x * 256 + threadIdx.x) >> 5;
    int lane = threadIdx.x & 31;
    if (warp >= TBROWS) return;
    const float* s;
    if (l0) { int b = warp & 63, t = warp >> 6; s = src + ((size_t)b * T_SEQ + t) * DIN; }
    else    { s = src + (size_t)warp * HIDN; }
    size_t o = (size_t)warp * Kpad;
    for (int k = lane; k < Kpad; k += 32) {
        float x = (k < K) ? s[k] : 0.f;
        __nv_bfloat16 h = __float2bfloat16(x);
        hi[o + k] = h;
        lo[o + k] = __float2bfloat16(x - __bfloat162float(h));
    }
}

// W [K][1800] -> transposed bf16 hi/lo [NPAD][Kpad] (zero-padded both dims)
__global__ void __launch_bounds__(256) conv_W(
    const float* __restrict__ W, __nv_bfloat16* __restrict__ hi,
    __nv_bfloat16* __restrict__ lo, int K, int Kpad)
{
    __shared__ float t[32][33];
    int k0 = blockIdx.x * 32, n0 = blockIdx.y * 32;
    int tx = threadIdx.x & 31, ty = threadIdx.x >> 5;
    #pragma unroll
    for (int i = 0; i < 4; i++) {
        int ky = k0 + ty + i * 8, n = n0 + tx;
        float v = 0.f;
        if (ky < K && n < G6) v = W[(size_t)ky * G6 + n];
        t[ty + i * 8][tx] = v;
    }
    __syncthreads();
    #pragma unroll
    for (int i = 0; i < 4; i++) {
        int n = n0 + ty + i * 8, k = k0 + tx;
        if (n < NPAD && k < Kpad) {
            float v = t[tx][ty + i * 8];
            __nv_bfloat16 h = __float2bfloat16(v);
            hi[(size_t)n * Kpad + k] = h;
            lo[(size_t)n * Kpad + k] = __float2bfloat16(v - __bfloat162float(h));
        }
    }
}

// ===================== split-bf16 HMMA GEMM =====================
// pi[bn+c][row] = sum_k A[row][k] * W[k][bn+c]
// CTA tile 128(M) x 128(N), K chunks of 32, double-buffered cp.async.
#define KC 32
#define PITCH 40                         // halves per smem row
#define TILE_H (128 * PITCH)             // halves per tile
#define STAGE_H (4 * TILE_H)             // Ah,Al,Bh,Bl
#define SMEM_GEMM_BYTES (2 * STAGE_H * 2)  // 81920

__global__ void __launch_bounds__(256) hgemm_tc(
    const __nv_bfloat16* __restrict__ Ah, const __nv_bfloat16* __restrict__ Al,
    const __nv_bfloat16* __restrict__ Bh, const __nv_bfloat16* __restrict__ Bl,
    float* __restrict__ pi, int Kpad, int nch)
{
    extern __shared__ __nv_bfloat16 sm[];
    const int tid = threadIdx.x, warp = tid >> 5, lane = tid & 31;
    const int bn = blockIdx.x * 128;
    const int bm = blockIdx.y * 128;
    const int wm = (warp >> 2) * 64;
    const int wn = (warp & 3) * 32;
    const uint32_t sb = smem_u32(sm);

    float acc[4][4][4];
    #pragma unroll
    for (int i = 0; i < 4; i++)
        #pragma unroll
        for (int j = 0; j < 4; j++)
            #pragma unroll
            for (int q = 0; q < 4; q++) acc[i][j][q] = 0.f;

    // tile loader: 2048 cp.async of 16B
    auto load_chunk = [&](int c, int s) {
        const int c0 = c * KC;
        const uint32_t sbase = sb + (uint32_t)s * STAGE_H * 2;
        #pragma unroll
        for (int it = 0; it < 8; it++) {
            int idx = it * 256 + tid;
            int tl  = idx >> 9;              // 0..3: Ah,Al,Bh,Bl
            int r   = (idx >> 2) & 127;
            int seg = idx & 3;
            const __nv_bfloat16* src;
            if      (tl == 0) src = Ah + ((size_t)(bm + r) * Kpad + c0);
            else if (tl == 1) src = Al + ((size_t)(bm + r) * Kpad + c0);
            else if (tl == 2) src = Bh + ((size_t)(bn + r) * Kpad + c0);
            else              src = Bl + ((size_t)(bn + r) * Kpad + c0);
            uint32_t dst = sbase + (uint32_t)(tl * TILE_H + r * PITCH + seg * 8) * 2;
            cp16(dst, src + seg * 8);
        }
    };

    load_chunk(0, 0);
    cp_commit();

    for (int c = 0; c < nch; c++) {
        if (c + 1 < nch) { load_chunk(c + 1, (c + 1) & 1); cp_commit(); cp_wait<1>(); }
        else             { cp_wait<0>(); }
        __syncthreads();

        const uint32_t st = sb + (uint32_t)(c & 1) * STAGE_H * 2;
        const uint32_t sAh = st, sAl = st + TILE_H * 2;
        const uint32_t sBh = st + 2 * TILE_H * 2, sBl = st + 3 * TILE_H * 2;

        #pragma unroll
        for (int ks = 0; ks < 2; ks++) {
            const int k0 = ks * 16;
            uint32_t ah[4][4], al[4][4], bh[4][2], bl[4][2];
            // A frags
            {
                int arow = lane & 15, akc = k0 + (lane >> 4) * 8;
                #pragma unroll
                for (int mt = 0; mt < 4; mt++) {
                    uint32_t off = (uint32_t)((wm + mt * 16 + arow) * PITCH + akc) * 2;
                    ldsm4(ah[mt], sAh + off);
                    ldsm4(al[mt], sAl + off);
                }
            }
            // B frags
            {
                int g = lane >> 3;
                int brow = ((g >= 2) ? 8 : 0) + (lane & 7);
                int bkc  = k0 + ((g & 1) ? 8 : 0);
                #pragma unroll
                for (int h = 0; h < 2; h++) {
                    uint32_t off = (uint32_t)((wn + h * 16 + brow) * PITCH + bkc) * 2;
                    uint32_t r4[4];
                    ldsm4(r4, sBh + off);
                    bh[h * 2 + 0][0] = r4[0]; bh[h * 2 + 0][1] = r4[1];
                    bh[h * 2 + 1][0] = r4[2]; bh[h * 2 + 1][1] = r4[3];
                    ldsm4(r4, sBl + off);
                    bl[h * 2 + 0][0] = r4[0]; bl[h * 2 + 0][1] = r4[1];
                    bl[h * 2 + 1][0] = r4[2]; bl[h * 2 + 1][1] = r4[3];
                }
            }
            // 3 passes (term-outer to break RAW chains on acc)
            #pragma unroll
            for (int mt = 0; mt < 4; mt++)
                #pragma unroll
                for (int nt = 0; nt < 4; nt++)
                    mma_bf16(acc[mt][nt], ah[mt], bh[nt]);
            #pragma unroll
            for (int mt = 0; mt < 4; mt++)
                #pragma unroll
                for (int nt = 0; nt < 4; nt++)
                    mma_bf16(acc[mt][nt], ah[mt], bl[nt]);
            #pragma unroll
            for (int mt = 0; mt < 4; mt++)
                #pragma unroll
                for (int nt = 0; nt < 4; nt++)
                    mma_bf16(acc[mt][nt], al[mt], bh[nt]);
        }
        __syncthreads();
    }

    // ---- epilogue: stage [col][row] in smem, then coalesced store ----
    float* scS = (float*)sm;                 // 128 cols x pitch 129
    #pragma unroll
    for (int mt = 0; mt < 4; mt++) {
        int grow = wm + mt * 16 + (lane >> 2);
        #pragma unroll
        for (int nt = 0; nt < 4; nt++) {
            int gcol = wn + nt * 8 + (lane & 3) * 2;
            scS[(size_t)gcol * 129 + grow]           = acc[mt][nt][0];
            scS[(size_t)(gcol + 1) * 129 + grow]     = acc[mt][nt][1];
            scS[(size_t)gcol * 129 + grow + 8]       = acc[mt][nt][2];
            scS[(size_t)(gcol + 1) * 129 + grow + 8] = acc[mt][nt][3];
        }
    }
    __syncthreads();
    for (int i = tid; i < 128 * 128; i += 256) {
        int col = i >> 7, row = i & 127;
        pi[(size_t)(bn + col) * TBROWS + (bm + row)] = scS[(size_t)col * 129 + row];
    }
}

// ===================== persistent recurrent scan (f32x2) =====================
__global__ void __launch_bounds__(256) lstm_scan(
    const float* __restrict__ Whh, const float* __restrict__ bias,
    const int* __restrict__ lengths, float* __restrict__ ys,
    int reverse, int* __restrict__ bar)
{
    __shared__ unsigned long long sW2[300 * 8];   // [k][8] packed f32 pairs (15 cols + pad)
    __shared__ float sred[4][64][17];

    const int tid = threadIdx.x;
    const int j0  = blockIdx.x * 3;
    const int b   = tid & 63;
    const int ks  = tid >> 6;

    for (int idx = tid; idx < 300 * 8; idx += 256) {
        int k = idx >> 3, c2 = idx & 7;
        float f0 = 0.f, f1 = 0.f;
        int c = 2 * c2;
        { int g = c / 3, jl = c % 3; f0 = Whh[(size_t)k * G5 + g * HIDN + j0 + jl]; }
        if (c + 1 < 15) {
            int g = (c + 1) / 3, jl = (c + 1) % 3;
            f1 = Whh[(size_t)k * G5 + g * HIDN + j0 + jl];
        }
        unsigned long long p;
        asm("mov.b64 %0, {%1,%2};" : "=l"(p) : "f"(f0), "f"(f1));
        sW2[idx] = p;
    }

    float c_st = 0.f, h_st = 0.f;
    float bi[5] = {0.f, 0.f, 0.f, 0.f, 0.f};
    int len = 0, jl = 0, jj = 0;
    if (tid < 192) {
        jl = tid >> 6;
        jj = j0 + jl;
        len = lengths[b];
        #pragma unroll
        for (int g = 0; g < 5; g++) bi[g] = bias[g * HIDN + jj];
    }
    __syncthreads();

    int p = 0;
    for (int t = 0; t < T_SEQ; t++) {
        unsigned long long acc2[8];
        #pragma unroll
        for (int i = 0; i < 8; i++) acc2[i] = 0ull;
        if (t > 0) {
            const float* hb = g_hbuf + p * (HIDN * BATCH);
            const int kbeg = ks * 75;
            #pragma unroll 5
            for (int k = kbeg; k < kbeg + 75; k++) {
                float hv = __ldcg(&hb[k * 64 + b]);
                unsigned long long hv2;
                asm("mov.b64 %0, {%1,%1};" : "=l"(hv2) : "f"(hv));
                const ulonglong2* w2 = (const ulonglong2*)(sW2 + (k << 3));
                ulonglong2 q0 = w2[0], q1 = w2[1], q2 = w2[2], q3 = w2[3];
                asm("fma.rn.f32x2 %0, %1, %2, %0;" : "+l"(acc2[0]) : "l"(q0.x), "l"(hv2));
                asm("fma.rn.f32x2 %0, %1, %2, %0;" : "+l"(acc2[1]) : "l"(q0.y), "l"(hv2));
                asm("fma.rn.f32x2 %0, %1, %2, %0;" : "+l"(acc2[2]) : "l"(q1.x), "l"(hv2));
                asm("fma.rn.f32x2 %0, %1, %2, %0;" : "+l"(acc2[3]) : "l"(q1.y), "l"(hv2));
                asm("fma.rn.f32x2 %0, %1, %2, %0;" : "+l"(acc2[4]) : "l"(q2.x), "l"(hv2));
                asm("fma.rn.f32x2 %0, %1, %2, %0;" : "+l"(acc2[5]) : "l"(q2.y), "l"(hv2));
                asm("fma.rn.f32x2 %0, %1, %2, %0;" : "+l"(acc2[6]) : "l"(q3.x), "l"(hv2));
                asm("fma.rn.f32x2 %0, %1, %2, %0;" : "+l"(acc2[7]) : "l"(q3.y), "l"(hv2));
            }
        }
        #pragma unroll
        for (int i = 0; i < 8; i++) {
            float lo, hi;
            asm("mov.b64 {%0,%1}, %2;" : "=f"(lo), "=f"(hi) : "l"(acc2[i]));
            sred[ks][b][2 * i] = lo;
            if (2 * i + 1 < 15) sred[ks][b][2 * i + 1] = hi;
        }
        __syncthreads();

        if (tid < 192) {
            float z[5];
            #pragma unroll
            for (int g = 0; g < 5; g++) {
                int cc = g * 3 + jl;
                z[g] = bi[g] + sred[0][b][cc] + sred[1][b][cc]
                             + sred[2][b][cc] + sred[3][b][cc];
            }
            int tr  = reverse ? (len - 1 - t) : t;
            int trc = tr < 0 ? 0 : tr;
            const size_t rb = (size_t)trc * BATCH + b;
            z[0] += g_pi[(size_t)(           jj) * TBROWS + rb];
            z[1] += g_pi[(size_t)(    HIDN + jj) * TBROWS + rb];
            z[2] += g_pi[(size_t)(2 * HIDN + jj) * TBROWS + rb];
            z[3] += g_pi[(size_t)(3 * HIDN + jj) * TBROWS + rb];
            z[4] += g_pi[(size_t)(4 * HIDN + jj) * TBROWS + rb];
            float pih = g_pi[(size_t)(5 * HIDN + jj) * TBROWS + rb];

            float ig = 1.f / (1.f + __expf(-z[0]));
            float fg = 1.f / (1.f + __expf(-z[1]));
            float gg = tanhf(z[2]);
            float og = 1.f / (1.f + __expf(-z[3]));
            float rg = 1.f / (1.f + __expf(-z[4]));
            float cn = ig * gg + fg * c_st;
            float lo = og * tanhf(cn);
            float hn = rg * lo + (1.f - rg) * pih;

            if (t < len) {
                c_st = cn;
                h_st = hn;
                int tout = reverse ? tr : t;
                ys[((size_t)tout * BATCH + b) * HIDN + jj] = hn;
            } else {
                ys[((size_t)t * BATCH + b) * HIDN + jj] = 0.f;   // padding
            }
            __stcg(&g_hbuf[(1 - p) * (HIDN * BATCH) + jj * 64 + b], h_st);
        }

        __syncthreads();
        if (tid == 0) {
            int* ctr = bar + t;
            asm volatile("red.release.gpu.global.add.s32 [%0], 1;" :: "l"(ctr) : "memory");
            int v;
            do {
                asm volatile("ld.acquire.gpu.global.s32 %0, [%1];" : "=r"(v) : "l"(ctr) : "memory");
                if (v < NCTA_SCAN) __nanosleep(32);
            } while (v < NCTA_SCAN);
        }
        __syncthreads();
        p ^= 1;
    }
}

// ===================== output transpose =====================
__global__ void __launch_bounds__(256) transpose_out(
    const float* __restrict__ hid7, float* __restrict__ out)
{
    int i = blockIdx.x * 256 + threadIdx.x;
    if (i >= LAYER_SZ) return;
    int h = i % HIDN;
    int r = i / HIDN;
    int b = r % BATCH;
    int t = r / BATCH;
    out[((size_t)b * T_SEQ + t) * HIDN + h] = hid7[i];
}

// ===========================================================================
extern "C" void kernel_launch(void* const* d_in, const int* in_sizes, int n_in,
                              void* d_out, int out_size)
{
    const float* inputs  = (const float*)d_in[0];
    const int*   lengths = (const int*)  d_in[1];
    const float* Wih0    = (const float*)d_in[2];
    const float* Wihr    = (const float*)d_in[3];
    const float* Whh     = (const float*)d_in[4];
    const float* bhh     = (const float*)d_in[5];
    float* out    = (float*)d_out;
    float* hidden = out + OUT_SZ;

    int* barp = nullptr;
    cudaGetSymbolAddress((void**)&barp, g_bar);
    float* pip = nullptr;
    cudaGetSymbolAddress((void**)&pip, g_pi);
    __nv_bfloat16 *ahp, *alp, *whp, *wlp;
    cudaGetSymbolAddress((void**)&ahp, g_Ah);
    cudaGetSymbolAddress((void**)&alp, g_Al);
    cudaGetSymbolAddress((void**)&whp, g_Wh);
    cudaGetSymbolAddress((void**)&wlp, g_Wl);

    cudaFuncSetAttribute(hgemm_tc, cudaFuncAttributeMaxDynamicSharedMemorySize,
                         SMEM_GEMM_BYTES);

    cudaMemsetAsync(barp, 0, NLAYERS * T_SEQ * sizeof(int), 0);

    for (int l = 0; l < NLAYERS; l++) {
        const float* A;
        const float* Wih;
        int K, Kpad, nch, a_l0;
        if (l == 0) { A = inputs; Wih = Wih0; K = DIN; Kpad = 256; nch = 8; a_l0 = 1; }
        else {
            A = hidden + (size_t)(l - 1) * LAYER_SZ;
            Wih = Wihr + (size_t)(l - 1) * HIDN * G6;
            K = HIDN; Kpad = 320; nch = 10; a_l0 = 0;
        }

        conv_A<<<TBROWS / 8, 256>>>(A, ahp, alp, K, Kpad, a_l0);
        conv_W<<<dim3(Kpad / 32, NPAD / 32), 256>>>(Wih, whp, wlp, K, Kpad);

        hgemm_tc<<<dim3(NPAD / 128, TBROWS / 128), 256, SMEM_GEMM_BYTES>>>(
            ahp, alp, whp, wlp, pip, Kpad, nch);

        lstm_scan<<<NCTA_SCAN, 256>>>(
            Whh + (size_t)l * HIDN * G5,
            bhh + (size_t)l * G5,
            lengths,
            hidden + (size_t)l * LAYER_SZ,
            l & 1,
            barp + l * T_SEQ);
    }

    transpose_out<<<(LAYER_SZ + 255) / 256, 256>>>(
        hidden + (size_t)(NLAYERS - 1) * LAYER_SZ, out);
}

// round 6
// speedup vs baseline: 1.2961x; 1.1024x over previous
#include <cuda_runtime.h>
#include <cuda_bf16.h>
#include <cstdint>
#include <cstddef>

#define T_SEQ   256
#define BATCH   64
#define DIN     200
#define HIDN    300
#define NLAYERS 8
#define G5      1500
#define G6      1800
#define NPAD    1920
#define TBROWS  (T_SEQ*BATCH)           // 16384
#define OUT_SZ  (BATCH*T_SEQ*HIDN)
#define LAYER_SZ (T_SEQ*BATCH*HIDN)
#define NCTA_SCAN 100
#define KPAD_MAX 320
#define HK      304                     // padded hidden K for scan MMA
#define HPITCH  312                     // smem pitch (halves) = 624B, conflict-free LDSM

// ---- scratch (device globals; no runtime allocation allowed) ----
__device__ float         g_pi[(size_t)NPAD * TBROWS];   // TRANSPOSED: [col][t*64+b]
__device__ __nv_bfloat16 g_Ah[(size_t)TBROWS * KPAD_MAX];
__device__ __nv_bfloat16 g_Al[(size_t)TBROWS * KPAD_MAX];
__device__ __nv_bfloat16 g_Wh[(size_t)NPAD * KPAD_MAX];
__device__ __nv_bfloat16 g_Wl[(size_t)NPAD * KPAD_MAX];
__device__ __nv_bfloat16 g_hhi[2][BATCH * HK];          // h split hi, [p][b][k] (pad k zero)
__device__ __nv_bfloat16 g_hlo[2][BATCH * HK];          // h split lo
__device__ int           g_bar[NLAYERS * T_SEQ];

// ============================ PTX helpers ============================
__device__ __forceinline__ uint32_t smem_u32(const void* p) {
    uint32_t a;
    asm("{ .reg .u64 t; cvta.to.shared.u64 t, %1; cvt.u32.u64 %0, t; }"
        : "=r"(a) : "l"(p));
    return a;
}
__device__ __forceinline__ void cp16(uint32_t dst, const void* src) {
    asm volatile("cp.async.cg.shared.global [%0], [%1], 16;"
                 :: "r"(dst), "l"(src) : "memory");
}
__device__ __forceinline__ void cp_commit() {
    asm volatile("cp.async.commit_group;" ::: "memory");
}
template <int N>
__device__ __forceinline__ void cp_wait() {
    asm volatile("cp.async.wait_group %0;" :: "n"(N) : "memory");
}
__device__ __forceinline__ void ldsm4(uint32_t* r, uint32_t addr) {
    asm volatile("ldmatrix.sync.aligned.m8n8.x4.shared.b16 {%0,%1,%2,%3}, [%4];"
                 : "=r"(r[0]), "=r"(r[1]), "=r"(r[2]), "=r"(r[3]) : "r"(addr));
}
__device__ __forceinline__ void mma_bf16(float* c, const uint32_t* a, const uint32_t* b) {
    asm volatile(
        "mma.sync.aligned.m16n8k16.row.col.f32.bf16.bf16.f32 "
        "{%0,%1,%2,%3}, {%4,%5,%6,%7}, {%8,%9}, {%0,%1,%2,%3};"
        : "+f"(c[0]), "+f"(c[1]), "+f"(c[2]), "+f"(c[3])
        : "r"(a[0]), "r"(a[1]), "r"(a[2]), "r"(a[3]), "r"(b[0]), "r"(b[1]));
}

// ========================= conversion kernels =========================
__global__ void __launch_bounds__(256) conv_A(
    const float* __restrict__ src, __nv_bfloat16* __restrict__ hi,
    __nv_bfloat16* __restrict__ lo, int K, int Kpad, int l0)
{
    int warp = (blockIdx.x * 256 + threadIdx.x) >> 5;
    int lane = threadIdx.x & 31;
    if (warp >= TBROWS) return;
    const float* s;
    if (l0) { int b = warp & 63, t = warp >> 6; s = src + ((size_t)b * T_SEQ + t) * DIN; }
    else    { s = src + (size_t)warp * HIDN; }
    size_t o = (size_t)warp * Kpad;
    for (int k = lane; k < Kpad; k += 32) {
        float x = (k < K) ? s[k] : 0.f;
        __nv_bfloat16 h = __float2bfloat16(x);
        hi[o + k] = h;
        lo[o + k] = __float2bfloat16(x - __bfloat162float(h));
    }
}

// W [K][1800] -> transposed bf16 hi/lo [NPAD][Kpad]
__global__ void __launch_bounds__(256) conv_W(
    const float* __restrict__ W, __nv_bfloat16* __restrict__ hi,
    __nv_bfloat16* __restrict__ lo, int K, int Kpad)
{
    __shared__ float t[32][33];
    int k0 = blockIdx.x * 32, n0 = blockIdx.y * 32;
    int tx = threadIdx.x & 31, ty = threadIdx.x >> 5;
    #pragma unroll
    for (int i = 0; i < 4; i++) {
        int ky = k0 + ty + i * 8, n = n0 + tx;
        float v = 0.f;
        if (ky < K && n < G6) v = W[(size_t)ky * G6 + n];
        t[ty + i * 8][tx] = v;
    }
    __syncthreads();
    #pragma unroll
    for (int i = 0; i < 4; i++) {
        int n = n0 + ty + i * 8, k = k0 + tx;
        if (n < NPAD && k < Kpad) {
            float v = t[tx][ty + i * 8];
            __nv_bfloat16 h = __float2bfloat16(v);
            hi[(size_t)n * Kpad + k] = h;
            lo[(size_t)n * Kpad + k] = __float2bfloat16(v - __bfloat162float(h));
        }
    }
}

// ===================== split-bf16 HMMA GEMM (input projections) =====================
#define KC 32
#define PITCH 40
#define TILE_H (128 * PITCH)
#define STAGE_H (4 * TILE_H)
#define SMEM_GEMM_BYTES (2 * STAGE_H * 2)

__global__ void __launch_bounds__(256) hgemm_tc(
    const __nv_bfloat16* __restrict__ Ah, const __nv_bfloat16* __restrict__ Al,
    const __nv_bfloat16* __restrict__ Bh, const __nv_bfloat16* __restrict__ Bl,
    float* __restrict__ pi, int Kpad, int nch)
{
    extern __shared__ __nv_bfloat16 sm[];
    const int tid = threadIdx.x, warp = tid >> 5, lane = tid & 31;
    const int bn = blockIdx.x * 128;
    const int bm = blockIdx.y * 128;
    const int wm = (warp >> 2) * 64;
    const int wn = (warp & 3) * 32;
    const uint32_t sb = smem_u32(sm);

    float acc[4][4][4];
    #pragma unroll
    for (int i = 0; i < 4; i++)
        #pragma unroll
        for (int j = 0; j < 4; j++)
            #pragma unroll
            for (int q = 0; q < 4; q++) acc[i][j][q] = 0.f;

    auto load_chunk = [&](int c, int s) {
        const int c0 = c * KC;
        const uint32_t sbase = sb + (uint32_t)s * STAGE_H * 2;
        #pragma unroll
        for (int it = 0; it < 8; it++) {
            int idx = it * 256 + tid;
            int tl  = idx >> 9;
            int r   = (idx >> 2) & 127;
            int seg = idx & 3;
            const __nv_bfloat16* src;
            if      (tl == 0) src = Ah + ((size_t)(bm + r) * Kpad + c0);
            else if (tl == 1) src = Al + ((size_t)(bm + r) * Kpad + c0);
            else if (tl == 2) src = Bh + ((size_t)(bn + r) * Kpad + c0);
            else              src = Bl + ((size_t)(bn + r) * Kpad + c0);
            uint32_t dst = sbase + (uint32_t)(tl * TILE_H + r * PITCH + seg * 8) * 2;
            cp16(dst, src + seg * 8);
        }
    };

    load_chunk(0, 0);
    cp_commit();

    for (int c = 0; c < nch; c++) {
        if (c + 1 < nch) { load_chunk(c + 1, (c + 1) & 1); cp_commit(); cp_wait<1>(); }
        else             { cp_wait<0>(); }
        __syncthreads();

        const uint32_t st = sb + (uint32_t)(c & 1) * STAGE_H * 2;
        const uint32_t sAh = st, sAl = st + TILE_H * 2;
        const uint32_t sBh = st + 2 * TILE_H * 2, sBl = st + 3 * TILE_H * 2;

        #pragma unroll
        for (int ks = 0; ks < 2; ks++) {
            const int k0 = ks * 16;
            uint32_t ah[4][4], al[4][4], bh[4][2], bl[4][2];
            {
                int arow = lane & 15, akc = k0 + (lane >> 4) * 8;
                #pragma unroll
                for (int mt = 0; mt < 4; mt++) {
                    uint32_t off = (uint32_t)((wm + mt * 16 + arow) * PITCH + akc) * 2;
                    ldsm4(ah[mt], sAh + off);
                    ldsm4(al[mt], sAl + off);
                }
            }
            {
                int g = lane >> 3;
                int brow = ((g >= 2) ? 8 : 0) + (lane & 7);
                int bkc  = k0 + ((g & 1) ? 8 : 0);
                #pragma unroll
                for (int h = 0; h < 2; h++) {
                    uint32_t off = (uint32_t)((wn + h * 16 + brow) * PITCH + bkc) * 2;
                    uint32_t r4[4];
                    ldsm4(r4, sBh + off);
                    bh[h * 2 + 0][0] = r4[0]; bh[h * 2 + 0][1] = r4[1];
                    bh[h * 2 + 1][0] = r4[2]; bh[h * 2 + 1][1] = r4[3];
                    ldsm4(r4, sBl + off);
                    bl[h * 2 + 0][0] = r4[0]; bl[h * 2 + 0][1] = r4[1];
                    bl[h * 2 + 1][0] = r4[2]; bl[h * 2 + 1][1] = r4[3];
                }
            }
            #pragma unroll
            for (int mt = 0; mt < 4; mt++)
                #pragma unroll
                for (int nt = 0; nt < 4; nt++)
                    mma_bf16(acc[mt][nt], ah[mt], bh[nt]);
            #pragma unroll
            for (int mt = 0; mt < 4; mt++)
                #pragma unroll
                for (int nt = 0; nt < 4; nt++)
                    mma_bf16(acc[mt][nt], ah[mt], bl[nt]);
            #pragma unroll
            for (int mt = 0; mt < 4; mt++)
                #pragma unroll
                for (int nt = 0; nt < 4; nt++)
                    mma_bf16(acc[mt][nt], al[mt], bh[nt]);
        }
        __syncthreads();
    }

    float* scS = (float*)sm;                 // 128 cols x pitch 129
    #pragma unroll
    for (int mt = 0; mt < 4; mt++) {
        int grow = wm + mt * 16 + (lane >> 2);
        #pragma unroll
        for (int nt = 0; nt < 4; nt++) {
            int gcol = wn + nt * 8 + (lane & 3) * 2;
            scS[(size_t)gcol * 129 + grow]           = acc[mt][nt][0];
            scS[(size_t)(gcol + 1) * 129 + grow]     = acc[mt][nt][1];
            scS[(size_t)gcol * 129 + grow + 8]       = acc[mt][nt][2];
            scS[(size_t)(gcol + 1) * 129 + grow + 8] = acc[mt][nt][3];
        }
    }
    __syncthreads();
    for (int i = tid; i < 128 * 128; i += 256) {
        int col = i >> 7, row = i & 127;
        pi[(size_t)(bn + col) * TBROWS + (bm + row)] = scS[(size_t)col * 129 + row];
    }
}

// ===================== tensorized persistent recurrent scan =====================
// 100 CTAs x 3 j-cols. Per step: z[64,15] = h[64,300] @ W[300,15] via HMMA split-bf16.
#define OFF_AHI 0
#define OFF_ALO (OFF_AHI + BATCH * HPITCH * 2)          // 39936
#define OFF_BHI (OFF_ALO + BATCH * HPITCH * 2)          // 79872
#define OFF_BLO (OFF_BHI + 16 * HPITCH * 2)             // 89856
#define OFF_Z   (OFF_BLO + 16 * HPITCH * 2)             // 99840
#define SMEM_SCAN_BYTES (OFF_Z + 64 * 17 * 4)           // 104192

__global__ void __launch_bounds__(256) lstm_scan(
    const float* __restrict__ Whh, const float* __restrict__ bias,
    const int* __restrict__ lengths, float* __restrict__ ys,
    int reverse, int* __restrict__ bar)
{
    extern __shared__ char smem[];
    const uint32_t sb = smem_u32(smem);
    float* zsm = (float*)(smem + OFF_Z);                 // [64][17]
    __nv_bfloat16* sBhi = (__nv_bfloat16*)(smem + OFF_BHI);
    __nv_bfloat16* sBlo = (__nv_bfloat16*)(smem + OFF_BLO);

    const int tid  = threadIdx.x;
    const int warp = tid >> 5, lane = tid & 31;
    const int j0   = blockIdx.x * 3;
    const int wm   = (warp >> 1) * 16;                   // m-tile (batch rows)
    const int wn   = (warp & 1) * 8;                     // n-tile (z cols)

    // ---- stage Whh slice as bf16 hi/lo, layout [c][k], c = g*3+jl ----
    for (int idx = tid; idx < 16 * HK; idx += 256) {
        int c = idx / HK, kk = idx % HK;
        float v = 0.f;
        if (c < 15 && kk < HIDN) {
            int g = c / 3, jl = c % 3;
            v = Whh[(size_t)kk * G5 + g * HIDN + j0 + jl];
        }
        __nv_bfloat16 h = __float2bfloat16(v);
        sBhi[c * HPITCH + kk] = h;
        sBlo[c * HPITCH + kk] = __float2bfloat16(v - __bfloat162float(h));
    }

    // pointwise-owner state (tid < 192: one (b, jl) each)
    float c_st = 0.f, h_st = 0.f;
    float bi[5] = {0.f, 0.f, 0.f, 0.f, 0.f};
    int len = 0, jl = 0, jj = 0;
    const int b = tid & 63;
    if (tid < 192) {
        jl = tid >> 6;
        jj = j0 + jl;
        len = lengths[b];
        #pragma unroll
        for (int g = 0; g < 5; g++) bi[g] = bias[g * HIDN + jj];
    }
    __syncthreads();

    int p = 0;
    for (int t = 0; t < T_SEQ; t++) {
        // ---- prefetch pi gates (depend only on t) ----
        float pg[6];
        if (tid < 192) {
            int tr  = reverse ? (len - 1 - t) : t;
            int trc = tr < 0 ? 0 : tr;
            const size_t rb = (size_t)trc * BATCH + b;
            #pragma unroll
            for (int g = 0; g < 6; g++)
                pg[g] = g_pi[(size_t)(g * HIDN + jj) * TBROWS + rb];
        }

        if (t > 0) {
            // ---- cp.async h hi/lo tiles: [64][304] -> smem pitch 312 ----
            const __nv_bfloat16* hsrc_hi = g_hhi[p];
            const __nv_bfloat16* hsrc_lo = g_hlo[p];
            #pragma unroll
            for (int it = 0; it < 19; it++) {
                int idx = it * 256 + tid;          // 0..4863
                int lo_t = idx >= 2432;
                int rc = lo_t ? idx - 2432 : idx;
                int row = rc / 38, ch = rc % 38;
                const __nv_bfloat16* src = (lo_t ? hsrc_lo : hsrc_hi) + row * HK + ch * 8;
                uint32_t dst = sb + (lo_t ? OFF_ALO : OFF_AHI) + (uint32_t)(row * HPITCH + ch * 8) * 2;
                cp16(dst, src);
            }
            cp_commit();
            cp_wait<0>();
            __syncthreads();

            // ---- HMMA: 19 k-steps x 3 terms on 3 acc chains ----
            float a0[4], a1[4], a2[4];
            #pragma unroll
            for (int q = 0; q < 4; q++) { a0[q] = 0.f; a1[q] = 0.f; a2[q] = 0.f; }
            const int arow = lane & 15, akc0 = (lane >> 4) * 8;
            const int gB = lane >> 3;
            const int brow = ((gB >= 2) ? 8 : 0) + (lane & 7);
            const int bkc0 = (gB & 1) ? 8 : 0;
            const int sel = 2 * (warp & 1);
            #pragma unroll 4
            for (int ks = 0; ks < 19; ks++) {
                const int k0 = ks * 16;
                uint32_t ah[4], al[4], r4[4], bh[2], bl[2];
                uint32_t aoff = sb + (uint32_t)((wm + arow) * HPITCH + k0 + akc0) * 2;
                ldsm4(ah, aoff + OFF_AHI);
                ldsm4(al, aoff + OFF_ALO);
                uint32_t boff = sb + (uint32_t)(brow * HPITCH + k0 + bkc0) * 2;
                ldsm4(r4, boff + OFF_BHI);
                bh[0] = r4[sel]; bh[1] = r4[sel + 1];
                ldsm4(r4, boff + OFF_BLO);
                bl[0] = r4[sel]; bl[1] = r4[sel + 1];
                mma_bf16(a0, ah, bh);
                mma_bf16(a1, ah, bl);
                mma_bf16(a2, al, bh);
            }
            // ---- z -> smem ----
            {
                int r0 = wm + (lane >> 2);
                int c0 = wn + (lane & 3) * 2;
                zsm[r0 * 17 + c0]           = a0[0] + a1[0] + a2[0];
                zsm[r0 * 17 + c0 + 1]       = a0[1] + a1[1] + a2[1];
                zsm[(r0 + 8) * 17 + c0]     = a0[2] + a1[2] + a2[2];
                zsm[(r0 + 8) * 17 + c0 + 1] = a0[3] + a1[3] + a2[3];
            }
        }
        __syncthreads();

        // ---- pointwise gates ----
        if (tid < 192) {
            float z[5];
            #pragma unroll
            for (int g = 0; g < 5; g++) {
                float zr = (t > 0) ? zsm[b * 17 + g * 3 + jl] : 0.f;
                z[g] = bi[g] + zr + pg[g];
            }
            float ig = 1.f / (1.f + __expf(-z[0]));
            float fg = 1.f / (1.f + __expf(-z[1]));
            float gg = tanhf(z[2]);
            float og = 1.f / (1.f + __expf(-z[3]));
            float rg = 1.f / (1.f + __expf(-z[4]));
            float cn = ig * gg + fg * c_st;
            float lo = og * tanhf(cn);
            float hn = rg * lo + (1.f - rg) * pg[5];

            if (t < len) {
                c_st = cn;
                h_st = hn;
                int tr = reverse ? (len - 1 - t) : t;
                ys[((size_t)tr * BATCH + b) * HIDN + jj] = hn;
            } else {
                ys[((size_t)t * BATCH + b) * HIDN + jj] = 0.f;   // padding
            }
            // write h split for next step's MMA
            __nv_bfloat16 hh = __float2bfloat16(h_st);
            g_hhi[1 - p][b * HK + jj] = hh;
            g_hlo[1 - p][b * HK + jj] = __float2bfloat16(h_st - __bfloat162float(hh));
        }

        // ---- grid barrier ----
        __syncthreads();
        if (tid == 0) {
            int* ctr = bar + t;
            asm volatile("red.release.gpu.global.add.s32 [%0], 1;" :: "l"(ctr) : "memory");
            int v;
            do {
                asm volatile("ld.acquire.gpu.global.s32 %0, [%1];" : "=r"(v) : "l"(ctr) : "memory");
                if (v < NCTA_SCAN) __nanosleep(32);
            } while (v < NCTA_SCAN);
        }
        __syncthreads();
        p ^= 1;
    }
}

// ===================== output transpose =====================
__global__ void __launch_bounds__(256) transpose_out(
    const float* __restrict__ hid7, float* __restrict__ out)
{
    int i = blockIdx.x * 256 + threadIdx.x;
    if (i >= LAYER_SZ) return;
    int h = i % HIDN;
    int r = i / HIDN;
    int b = r % BATCH;
    int t = r / BATCH;
    out[((size_t)b * T_SEQ + t) * HIDN + h] = hid7[i];
}

// ===========================================================================
extern "C" void kernel_launch(void* const* d_in, const int* in_sizes, int n_in,
                              void* d_out, int out_size)
{
    const float* inputs  = (const float*)d_in[0];
    const int*   lengths = (const int*)  d_in[1];
    const float* Wih0    = (const float*)d_in[2];
    const float* Wihr    = (const float*)d_in[3];
    const float* Whh     = (const float*)d_in[4];
    const float* bhh     = (const float*)d_in[5];
    float* out    = (float*)d_out;
    float* hidden = out + OUT_SZ;

    int* barp = nullptr;
    cudaGetSymbolAddress((void**)&barp, g_bar);
    float* pip = nullptr;
    cudaGetSymbolAddress((void**)&pip, g_pi);
    __nv_bfloat16 *ahp, *alp, *whp, *wlp;
    cudaGetSymbolAddress((void**)&ahp, g_Ah);
    cudaGetSymbolAddress((void**)&alp, g_Al);
    cudaGetSymbolAddress((void**)&whp, g_Wh);
    cudaGetSymbolAddress((void**)&wlp, g_Wl);

    cudaFuncSetAttribute(hgemm_tc, cudaFuncAttributeMaxDynamicSharedMemorySize,
                         SMEM_GEMM_BYTES);
    cudaFuncSetAttribute(lstm_scan, cudaFuncAttributeMaxDynamicSharedMemorySize,
                         SMEM_SCAN_BYTES);

    cudaMemsetAsync(barp, 0, NLAYERS * T_SEQ * sizeof(int), 0);

    for (int l = 0; l < NLAYERS; l++) {
        const float* A;
        const float* Wih;
        int K, Kpad, nch, a_l0;
        if (l == 0) { A = inputs; Wih = Wih0; K = DIN; Kpad = 256; nch = 8; a_l0 = 1; }
        else {
            A = hidden + (size_t)(l - 1) * LAYER_SZ;
            Wih = Wihr + (size_t)(l - 1) * HIDN * G6;
            K = HIDN; Kpad = 320; nch = 10; a_l0 = 0;
        }

        conv_A<<<TBROWS / 8, 256>>>(A, ahp, alp, K, Kpad, a_l0);
        conv_W<<<dim3(Kpad / 32, NPAD / 32), 256>>>(Wih, whp, wlp, K, Kpad);

        hgemm_tc<<<dim3(NPAD / 128, TBROWS / 128), 256, SMEM_GEMM_BYTES>>>(
            ahp, alp, whp, wlp, pip, Kpad, nch);

        lstm_scan<<<NCTA_SCAN, 256, SMEM_SCAN_BYTES>>>(
            Whh + (size_t)l * HIDN * G5,
            bhh + (size_t)l * G5,
            lengths,
            hidden + (size_t)l * LAYER_SZ,
            l & 1,
            barp + l * T_SEQ);
    }

    transpose_out<<<(LAYER_SZ + 255) / 256, 256>>>(
        hidden + (size_t)(NLAYERS - 1) * LAYER_SZ, out);
}

// round 9
// speedup vs baseline: 2.1264x; 1.6406x over previous
#include <cuda_runtime.h>
#include <cuda_bf16.h>
#include <cstdint>
#include <cstddef>

#define T_SEQ   256
#define BATCH   64
#define DIN     200
#define HIDN    300
#define NLAYERS 8
#define G5      1500
#define G6      1800
#define NPAD    1920
#define TBROWS  (T_SEQ*BATCH)           // 16384
#define OUT_SZ  (BATCH*T_SEQ*HIDN)
#define LAYER_SZ (T_SEQ*BATCH*HIDN)
#define KPAD_MAX 320

// scan partitioning: 4 batch-groups x 25 column-CTAs
#define NGRP    4
#define GB      16                      // batches per group
#define NCOL    25                      // CTAs per group
#define JPC     12                      // j-columns per CTA
#define SHK     320                     // padded K for scan MMA (20 k-steps)
#define SHP     328                     // smem pitch halves (656B: conflict-free LDSM)

// ---- scratch (device globals; no runtime allocation allowed) ----
__device__ float         g_pi[(size_t)NPAD * TBROWS];   // TRANSPOSED: [col][t*64+b]
__device__ __nv_bfloat16 g_Ah[(size_t)TBROWS * KPAD_MAX];
__device__ __nv_bfloat16 g_Al[(size_t)TBROWS * KPAD_MAX];
__device__ __nv_bfloat16 g_Wh[(size_t)NPAD * KPAD_MAX];
__device__ __nv_bfloat16 g_Wl[(size_t)NPAD * KPAD_MAX];
__device__ __nv_bfloat16 g_hhi[NGRP * 2 * GB * SHK];    // [grp][p][b][k]
__device__ __nv_bfloat16 g_hlo[NGRP * 2 * GB * SHK];
__device__ int           g_bar[NLAYERS * NGRP * T_SEQ];

// ============================ PTX helpers ============================
__device__ __forceinline__ uint32_t smem_u32(const void* p) {
    uint32_t a;
    asm("{ .reg .u64 t; cvta.to.shared.u64 t, %1; cvt.u32.u64 %0, t; }"
        : "=r"(a) : "l"(p));
    return a;
}
__device__ __forceinline__ void cp16(uint32_t dst, const void* src) {
    asm volatile("cp.async.cg.shared.global [%0], [%1], 16;"
                 :: "r"(dst), "l"(src) : "memory");
}
__device__ __forceinline__ void cp_commit() {
    asm volatile("cp.async.commit_group;" ::: "memory");
}
template <int N>
__device__ __forceinline__ void cp_wait() {
    asm volatile("cp.async.wait_group %0;" :: "n"(N) : "memory");
}
__device__ __forceinline__ void ldsm4(uint32_t* r, uint32_t addr) {
    asm volatile("ldmatrix.sync.aligned.m8n8.x4.shared.b16 {%0,%1,%2,%3}, [%4];"
                 : "=r"(r[0]), "=r"(r[1]), "=r"(r[2]), "=r"(r[3]) : "r"(addr));
}
__device__ __forceinline__ void mma_bf16(float* c, const uint32_t* a, const uint32_t* b) {
    asm volatile(
        "mma.sync.aligned.m16n8k16.row.col.f32.bf16.bf16.f32 "
        "{%0,%1,%2,%3}, {%4,%5,%6,%7}, {%8,%9}, {%0,%1,%2,%3};"
        : "+f"(c[0]), "+f"(c[1]), "+f"(c[2]), "+f"(c[3])
        : "r"(a[0]), "r"(a[1]), "r"(a[2]), "r"(a[3]), "r"(b[0]), "r"(b[1]));
}

// ========================= conversion kernels =========================
__global__ void __launch_bounds__(256) conv_A(
    const float* __restrict__ src, __nv_bfloat16* __restrict__ hi,
    __nv_bfloat16* __restrict__ lo, int K, int Kpad, int l0)
{
    int warp = (blockIdx.x * 256 + threadIdx.x) >> 5;
    int lane = threadIdx.x & 31;
    if (warp >= TBROWS) return;
    const float* s;
    if (l0) { int b = warp & 63, t = warp >> 6; s = src + ((size_t)b * T_SEQ + t) * DIN; }
    else    { s = src + (size_t)warp * HIDN; }
    size_t o = (size_t)warp * Kpad;
    for (int k = lane; k < Kpad; k += 32) {
        float x = (k < K) ? s[k] : 0.f;
        __nv_bfloat16 h = __float2bfloat16(x);
        hi[o + k] = h;
        lo[o + k] = __float2bfloat16(x - __bfloat162float(h));
    }
}

// W [K][1800] -> transposed bf16 hi/lo [NPAD][Kpad]
__global__ void __launch_bounds__(256) conv_W(
    const float* __restrict__ W, __nv_bfloat16* __restrict__ hi,
    __nv_bfloat16* __restrict__ lo, int K, int Kpad)
{
    __shared__ float t[32][33];
    int k0 = blockIdx.x * 32, n0 = blockIdx.y * 32;
    int tx = threadIdx.x & 31, ty = threadIdx.x >> 5;
    #pragma unroll
    for (int i = 0; i < 4; i++) {
        int ky = k0 + ty + i * 8, n = n0 + tx;
        float v = 0.f;
        if (ky < K && n < G6) v = W[(size_t)ky * G6 + n];
        t[ty + i * 8][tx] = v;
    }
    __syncthreads();
    #pragma unroll
    for (int i = 0; i < 4; i++) {
        int n = n0 + ty + i * 8, k = k0 + tx;
        if (n < NPAD && k < Kpad) {
            float v = t[tx][ty + i * 8];
            __nv_bfloat16 h = __float2bfloat16(v);
            hi[(size_t)n * Kpad + k] = h;
            lo[(size_t)n * Kpad + k] = __float2bfloat16(v - __bfloat162float(h));
        }
    }
}

// ===================== split-bf16 HMMA GEMM (input projections) =====================
#define KC 32
#define PITCH 40
#define TILE_H (128 * PITCH)
#define STAGE_H (4 * TILE_H)
#define SMEM_GEMM_BYTES (2 * STAGE_H * 2)

__global__ void __launch_bounds__(256) hgemm_tc(
    const __nv_bfloat16* __restrict__ Ah, const __nv_bfloat16* __restrict__ Al,
    const __nv_bfloat16* __restrict__ Bh, const __nv_bfloat16* __restrict__ Bl,
    float* __restrict__ pi, int Kpad, int nch)
{
    extern __shared__ __nv_bfloat16 sm[];
    const int tid = threadIdx.x, warp = tid >> 5, lane = tid & 31;
    const int bn = blockIdx.x * 128;
    const int bm = blockIdx.y * 128;
    const int wm = (warp >> 2) * 64;
    const int wn = (warp & 3) * 32;
    const uint32_t sb = smem_u32(sm);

    float acc[4][4][4];
    #pragma unroll
    for (int i = 0; i < 4; i++)
        #pragma unroll
        for (int j = 0; j < 4; j++)
            #pragma unroll
            for (int q = 0; q < 4; q++) acc[i][j][q] = 0.f;

    auto load_chunk = [&](int c, int s) {
        const int c0 = c * KC;
        const uint32_t sbase = sb + (uint32_t)s * STAGE_H * 2;
        #pragma unroll
        for (int it = 0; it < 8; it++) {
            int idx = it * 256 + tid;
            int tl  = idx >> 9;
            int r   = (idx >> 2) & 127;
            int seg = idx & 3;
            const __nv_bfloat16* src;
            if      (tl == 0) src = Ah + ((size_t)(bm + r) * Kpad + c0);
            else if (tl == 1) src = Al + ((size_t)(bm + r) * Kpad + c0);
            else if (tl == 2) src = Bh + ((size_t)(bn + r) * Kpad + c0);
            else              src = Bl + ((size_t)(bn + r) * Kpad + c0);
            uint32_t dst = sbase + (uint32_t)(tl * TILE_H + r * PITCH + seg * 8) * 2;
            cp16(dst, src + seg * 8);
        }
    };

    load_chunk(0, 0);
    cp_commit();

    for (int c = 0; c < nch; c++) {
        if (c + 1 < nch) { load_chunk(c + 1, (c + 1) & 1); cp_commit(); cp_wait<1>(); }
        else             { cp_wait<0>(); }
        __syncthreads();

        const uint32_t st = sb + (uint32_t)(c & 1) * STAGE_H * 2;
        const uint32_t sAh = st, sAl = st + TILE_H * 2;
        const uint32_t sBh = st + 2 * TILE_H * 2, sBl = st + 3 * TILE_H * 2;

        #pragma unroll
        for (int ks = 0; ks < 2; ks++) {
            const int k0 = ks * 16;
            uint32_t ah[4][4], al[4][4], bh[4][2], bl[4][2];
            {
                int arow = lane & 15, akc = k0 + (lane >> 4) * 8;
                #pragma unroll
                for (int mt = 0; mt < 4; mt++) {
                    uint32_t off = (uint32_t)((wm + mt * 16 + arow) * PITCH + akc) * 2;
                    ldsm4(ah[mt], sAh + off);
                    ldsm4(al[mt], sAl + off);
                }
            }
            {
                int g = lane >> 3;
                int brow = ((g >= 2) ? 8 : 0) + (lane & 7);
                int bkc  = k0 + ((g & 1) ? 8 : 0);
                #pragma unroll
                for (int h = 0; h < 2; h++) {
                    uint32_t off = (uint32_t)((wn + h * 16 + brow) * PITCH + bkc) * 2;
                    uint32_t r4[4];
                    ldsm4(r4, sBh + off);
                    bh[h * 2 + 0][0] = r4[0]; bh[h * 2 + 0][1] = r4[1];
                    bh[h * 2 + 1][0] = r4[2]; bh[h * 2 + 1][1] = r4[3];
                    ldsm4(r4, sBl + off);
                    bl[h * 2 + 0][0] = r4[0]; bl[h * 2 + 0][1] = r4[1];
                    bl[h * 2 + 1][0] = r4[2]; bl[h * 2 + 1][1] = r4[3];
                }
            }
            #pragma unroll
            for (int mt = 0; mt < 4; mt++)
                #pragma unroll
                for (int nt = 0; nt < 4; nt++)
                    mma_bf16(acc[mt][nt], ah[mt], bh[nt]);
            #pragma unroll
            for (int mt = 0; mt < 4; mt++)
                #pragma unroll
                for (int nt = 0; nt < 4; nt++)
                    mma_bf16(acc[mt][nt], ah[mt], bl[nt]);
            #pragma unroll
            for (int mt = 0; mt < 4; mt++)
                #pragma unroll
                for (int nt = 0; nt < 4; nt++)
                    mma_bf16(acc[mt][nt], al[mt], bh[nt]);
        }
        __syncthreads();
    }

    float* scS = (float*)sm;                 // 128 cols x pitch 129
    #pragma unroll
    for (int mt = 0; mt < 4; mt++) {
        int grow = wm + mt * 16 + (lane >> 2);
        #pragma unroll
        for (int nt = 0; nt < 4; nt++) {
            int gcol = wn + nt * 8 + (lane & 3) * 2;
            scS[(size_t)gcol * 129 + grow]           = acc[mt][nt][0];
            scS[(size_t)(gcol + 1) * 129 + grow]     = acc[mt][nt][1];
            scS[(size_t)gcol * 129 + grow + 8]       = acc[mt][nt][2];
            scS[(size_t)(gcol + 1) * 129 + grow + 8] = acc[mt][nt][3];
        }
    }
    __syncthreads();
    for (int i = tid; i < 128 * 128; i += 256) {
        int col = i >> 7, row = i & 127;
        pi[(size_t)(bn + col) * TBROWS + (bm + row)] = scS[(size_t)col * 129 + row];
    }
}

// ===================== grouped tensorized recurrent scan =====================
// grid = 100: grp = blk/25 (16 batches), cidx = blk%25 (12 j-cols).
// Per step: z[16, 60] = h[16,300] @ W[300,60], split-bf16 HMMA.
#define OFF_HHI 0
#define OFF_HLO (GB * SHP * 2)                  // 10496
#define OFF_WHI (2 * GB * SHP * 2)              // 20992
#define OFF_WLO (OFF_WHI + 64 * SHP * 2)        // 62976
#define OFF_Z   (OFF_WLO + 64 * SHP * 2)        // 104960
#define SMEM_SCAN_BYTES (OFF_Z + GB * 68 * 4)   // 109312

__global__ void __launch_bounds__(256) lstm_scan(
    const float* __restrict__ Whh, const float* __restrict__ bias,
    const int* __restrict__ lengths, float* __restrict__ ys,
    int reverse, int* __restrict__ bar)
{
    extern __shared__ char smem[];
    const uint32_t sb = smem_u32(smem);
    float* zsm = (float*)(smem + OFF_Z);            // [16][68]
    __nv_bfloat16* sWhi = (__nv_bfloat16*)(smem + OFF_WHI);
    __nv_bfloat16* sWlo = (__nv_bfloat16*)(smem + OFF_WLO);

    const int tid = threadIdx.x, warp = tid >> 5, lane = tid & 31;
    const int grp  = blockIdx.x / NCOL;
    const int cidx = blockIdx.x % NCOL;
    const int j0   = cidx * JPC;
    const int wn   = warp * 8;

    // ---- stage W slice [c][k], c = g*12+jl (64 cols, 60 used) ----
    for (int idx = tid; idx < 64 * SHK; idx += 256) {
        int c = idx / SHK, k = idx % SHK;
        float v = 0.f;
        if (c < 60 && k < HIDN)
            v = Whh[(size_t)k * G5 + (c / JPC) * HIDN + j0 + (c % JPC)];
        __nv_bfloat16 h = __float2bfloat16(v);
        sWhi[c * SHP + k] = h;
        sWlo[c * SHP + k] = __float2bfloat16(v - __bfloat162float(h));
    }

    // pointwise owners: tid<192 -> (jl = tid/16, b = tid%16)
    const int b  = tid & 15;
    const int jl = tid >> 4;
    const int bg = grp * GB + b;
    float c_st = 0.f, h_st = 0.f;
    float bi[5] = {0.f, 0.f, 0.f, 0.f, 0.f};
    int len = 0, jj = 0;
    if (tid < 192) {
        jj = j0 + jl;
        len = lengths[bg];
        #pragma unroll
        for (int g = 0; g < 5; g++) bi[g] = bias[g * HIDN + jj];
    }
    const int Tg = lengths[grp * GB];      // max length in group (sorted desc)
    int* const ctr_base = bar + grp * T_SEQ;
    __syncthreads();

    int p = 0;
    for (int t = 0; t < Tg; t++) {
        // ---- issue h-tile cp.async first (if needed) ----
        if (t > 0) {
            const __nv_bfloat16* hhi = g_hhi + (size_t)(grp * 2 + p) * (GB * SHK);
            const __nv_bfloat16* hlo = g_hlo + (size_t)(grp * 2 + p) * (GB * SHK);
            #pragma unroll
            for (int it = 0; it < 5; it++) {
                int idx = it * 256 + tid;          // 0..1279
                int lo_t = idx >= 640;
                int rc = lo_t ? idx - 640 : idx;
                int row = rc / 40, ch = rc % 40;
                const __nv_bfloat16* src = (lo_t ? hlo : hhi) + row * SHK + ch * 8;
                uint32_t dst = sb + (lo_t ? OFF_HLO : OFF_HHI)
                             + (uint32_t)(row * SHP + ch * 8) * 2;
                cp16(dst, src);
            }
            cp_commit();
        }

        // ---- pg prefetch overlaps the cp.async ----
        float pg[6];
        if (tid < 192) {
            int tr  = reverse ? (len - 1 - t) : t;
            int trc = tr < 0 ? 0 : tr;
            const size_t rb = (size_t)trc * BATCH + bg;
            #pragma unroll
            for (int g = 0; g < 6; g++)
                pg[g] = g_pi[(size_t)(g * HIDN + jj) * TBROWS + rb];
        }

        if (t > 0) {
            cp_wait<0>();
            __syncthreads();

            // ---- HMMA: 10 k-pairs (20 ks) x 3 terms on 3 acc chains ----
            float a0[4] = {0.f, 0.f, 0.f, 0.f};
            float a1[4] = {0.f, 0.f, 0.f, 0.f};
            float a2[4] = {0.f, 0.f, 0.f, 0.f};
            const int arow = lane & 15, akc0 = (lane >> 4) * 8;
            const int bro = wn + (lane & 7), bko = (lane >> 3) * 8;
            #pragma unroll
            for (int kp = 0; kp < 10; kp++) {
                const int k0 = kp * 32;
                uint32_t ah0[4], al0[4], ah1[4], al1[4], rbh[4], rbl[4];
                uint32_t aoff = (uint32_t)(arow * SHP + k0 + akc0) * 2;
                ldsm4(ah0, sb + OFF_HHI + aoff);
                ldsm4(al0, sb + OFF_HLO + aoff);
                ldsm4(ah1, sb + OFF_HHI + aoff + 32);
                ldsm4(al1, sb + OFF_HLO + aoff + 32);
                uint32_t boff = (uint32_t)(bro * SHP + k0 + bko) * 2;
                ldsm4(rbh, sb + OFF_WHI + boff);
                ldsm4(rbl, sb + OFF_WLO + boff);
                mma_bf16(a0, ah0, rbh);
                mma_bf16(a1, ah0, rbl);
                mma_bf16(a2, al0, rbh);
                mma_bf16(a0, ah1, rbh + 2);
                mma_bf16(a1, ah1, rbl + 2);
                mma_bf16(a2, al1, rbh + 2);
            }
            int r0 = lane >> 2, c0 = wn + (lane & 3) * 2;
            zsm[r0 * 68 + c0]           = a0[0] + a1[0] + a2[0];
            zsm[r0 * 68 + c0 + 1]       = a0[1] + a1[1] + a2[1];
            zsm[(r0 + 8) * 68 + c0]     = a0[2] + a1[2] + a2[2];
            zsm[(r0 + 8) * 68 + c0 + 1] = a0[3] + a1[3] + a2[3];
        }
        __syncthreads();

        // ---- pointwise gates ----
        if (tid < 192) {
            float z[5];
            #pragma unroll
            for (int g = 0; g < 5; g++) {
                float zr = (t > 0) ? zsm[b * 68 + g * JPC + jl] : 0.f;
                z[g] = bi[g] + zr + pg[g];
            }
            float ig = 1.f / (1.f + __expf(-z[0]));
            float fg = 1.f / (1.f + __expf(-z[1]));
            float gg = tanhf(z[2]);
            float og = 1.f / (1.f + __expf(-z[3]));
            float rg = 1.f / (1.f + __expf(-z[4]));
            float cn = ig * gg + fg * c_st;
            float lo = og * tanhf(cn);
            float hn = rg * lo + (1.f - rg) * pg[5];

            if (t < len) {
                c_st = cn;
                h_st = hn;
                int tr = reverse ? (len - 1 - t) : t;
                ys[((size_t)tr * BATCH + bg) * HIDN + jj] = hn;
            }
            __nv_bfloat16 hh = __float2bfloat16(h_st);
            size_t ho = (size_t)(grp * 2 + (1 - p)) * (GB * SHK) + b * SHK + jj;
            g_hhi[ho] = hh;
            g_hlo[ho] = __float2bfloat16(h_st - __bfloat162float(hh));
        }

        // ---- group barrier (25 CTAs) ----
        __syncthreads();
        if (tid == 0) {
            int* ctr = ctr_base + t;
            asm volatile("red.release.gpu.global.add.s32 [%0], 1;" :: "l"(ctr) : "memory");
            int v;
            do {
                asm volatile("ld.acquire.gpu.global.s32 %0, [%1];" : "=r"(v) : "l"(ctr) : "memory");
                if (v < NCOL) __nanosleep(20);
            } while (v < NCOL);
        }
        __syncthreads();
        p ^= 1;
    }
}

// ===================== padding zero-fill =====================
__global__ void __launch_bounds__(256) pad_fill(
    float* __restrict__ hid, const int* __restrict__ lengths)
{
    int i = blockIdx.x * 256 + threadIdx.x;
    if (i >= LAYER_SZ) return;
    int r = i / HIDN;
    int b = r % BATCH;
    int t = r / BATCH;
    if (t >= lengths[b]) hid[i] = 0.f;
}

// ===================== output transpose =====================
__global__ void __launch_bounds__(256) transpose_out(
    const float* __restrict__ hid7, float* __restrict__ out)
{
    int i = blockIdx.x * 256 + threadIdx.x;
    if (i >= LAYER_SZ) return;
    int h = i % HIDN;
    int r = i / HIDN;
    int b = r % BATCH;
    int t = r / BATCH;
    out[((size_t)b * T_SEQ + t) * HIDN + h] = hid7[i];
}

// ===========================================================================
extern "C" void kernel_launch(void* const* d_in, const int* in_sizes, int n_in,
                              void* d_out, int out_size)
{
    const float* inputs  = (const float*)d_in[0];
    const int*   lengths = (const int*)  d_in[1];
    const float* Wih0    = (const float*)d_in[2];
    const float* Wihr    = (const float*)d_in[3];
    const float* Whh     = (const float*)d_in[4];
    const float* bhh     = (const float*)d_in[5];
    float* out    = (float*)d_out;
    float* hidden = out + OUT_SZ;

    int* barp = nullptr;
    cudaGetSymbolAddress((void**)&barp, g_bar);
    float* pip = nullptr;
    cudaGetSymbolAddress((void**)&pip, g_pi);
    __nv_bfloat16 *ahp, *alp, *whp, *wlp;
    cudaGetSymbolAddress((void**)&ahp, g_Ah);
    cudaGetSymbolAddress((void**)&alp, g_Al);
    cudaGetSymbolAddress((void**)&whp, g_Wh);
    cudaGetSymbolAddress((void**)&wlp, g_Wl);

    cudaFuncSetAttribute(hgemm_tc, cudaFuncAttributeMaxDynamicSharedMemorySize,
                         SMEM_GEMM_BYTES);
    cudaFuncSetAttribute(lstm_scan, cudaFuncAttributeMaxDynamicSharedMemorySize,
                         SMEM_SCAN_BYTES);

    cudaMemsetAsync(barp, 0, NLAYERS * NGRP * T_SEQ * sizeof(int), 0);

    for (int l = 0; l < NLAYERS; l++) {
        const float* A;
        const float* Wih;
        int K, Kpad, nch, a_l0;
        if (l == 0) { A = inputs; Wih = Wih0; K = DIN; Kpad = 256; nch = 8; a_l0 = 1; }
        else {
            A = hidden + (size_t)(l - 1) * LAYER_SZ;
            Wih = Wihr + (size_t)(l - 1) * HIDN * G6;
            K = HIDN; Kpad = 320; nch = 10; a_l0 = 0;
        }

        conv_A<<<TBROWS / 8, 256>>>(A, ahp, alp, K, Kpad, a_l0);
        conv_W<<<dim3(Kpad / 32, NPAD / 32), 256>>>(Wih, whp, wlp, K, Kpad);

        hgemm_tc<<<dim3(NPAD / 128, TBROWS / 128), 256, SMEM_GEMM_BYTES>>>(
            ahp, alp, whp, wlp, pip, Kpad, nch);

        lstm_scan<<<NGRP * NCOL, 256, SMEM_SCAN_BYTES>>>(
            Whh + (size_t)l * HIDN * G5,
            bhh + (size_t)l * G5,
            lengths,
            hidden + (size_t)l * LAYER_SZ,
            l & 1,
            barp + l * NGRP * T_SEQ);

        pad_fill<<<(LAYER_SZ + 255) / 256, 256>>>(
            hidden + (size_t)l * LAYER_SZ, lengths);
    }

    transpose_out<<<(LAYER_SZ + 255) / 256, 256>>>(
        hidden + (size_t)(NLAYERS - 1) * LAYER_SZ, out);
}